// round 9
// baseline (speedup 1.0000x reference)
#include <cuda_runtime.h>
#include <math_constants.h>

#define NPIX_MAX (32 * 128 * 2048)
#define TB 256

__device__ float        g_gray[NPIX_MAX];
__device__ unsigned int g_min_bits;
__device__ unsigned int g_max_bits;
__device__ unsigned int g_hist[256];

__device__ __forceinline__ unsigned int f_enc(float f) {
    unsigned int u = __float_as_uint(f);
    return (u & 0x80000000u) ? ~u : (u | 0x80000000u);
}
__device__ __forceinline__ float f_dec(unsigned int e) {
    unsigned int u = (e & 0x80000000u) ? (e & 0x7FFFFFFFu) : ~e;
    return __uint_as_float(u);
}
__device__ __forceinline__ float gray_of(float r, float g, float b) {
    return fmaf(0.1140f, b, fmaf(0.5870f, g, __fmul_rn(0.2989f, r)));
}

// ---------------- K0: reset state (inside graph, every replay) -------------
__global__ void init_kernel() {
    int t = threadIdx.x;
    if (t < 256) g_hist[t] = 0u;
    if (t == 0) {
        g_min_bits = 0xFFFFFFFFu;
        g_max_bits = 0x00000000u;
    }
}

// ---------------- K1: gray + min/max (direct loads, no barriers) -----------
__global__ void gray_minmax_kernel(const float* __restrict__ in, int npix) {
    const int ngroups = npix >> 2;
    const int stride  = gridDim.x * blockDim.x;
    const float4* __restrict__ in4 = (const float4*)in;
    float4* __restrict__ gr4 = (float4*)g_gray;
    const int t = threadIdx.x;

    float lmin = CUDART_INF_F, lmax = -CUDART_INF_F;

    int g = blockIdx.x * blockDim.x + t;
    // 2-way manual unroll for MLP
    for (; g + stride < ngroups; g += 2 * stride) {
        float4 a0 = in4[3 * g + 0];
        float4 b0 = in4[3 * g + 1];
        float4 c0 = in4[3 * g + 2];
        int g1i = g + stride;
        float4 a1 = in4[3 * g1i + 0];
        float4 b1 = in4[3 * g1i + 1];
        float4 c1 = in4[3 * g1i + 2];

        float x0 = gray_of(a0.x, a0.y, a0.z);
        float x1 = gray_of(a0.w, b0.x, b0.y);
        float x2 = gray_of(b0.z, b0.w, c0.x);
        float x3 = gray_of(c0.y, c0.z, c0.w);
        gr4[g] = make_float4(x0, x1, x2, x3);

        float y0 = gray_of(a1.x, a1.y, a1.z);
        float y1 = gray_of(a1.w, b1.x, b1.y);
        float y2 = gray_of(b1.z, b1.w, c1.x);
        float y3 = gray_of(c1.y, c1.z, c1.w);
        gr4[g1i] = make_float4(y0, y1, y2, y3);

        lmin = fminf(lmin, fminf(fminf(fminf(x0, x1), fminf(x2, x3)),
                                 fminf(fminf(y0, y1), fminf(y2, y3))));
        lmax = fmaxf(lmax, fmaxf(fmaxf(fmaxf(x0, x1), fmaxf(x2, x3)),
                                 fmaxf(fmaxf(y0, y1), fmaxf(y2, y3))));
    }
    for (; g < ngroups; g += stride) {
        float4 a = in4[3 * g + 0];
        float4 b = in4[3 * g + 1];
        float4 c = in4[3 * g + 2];
        float x0 = gray_of(a.x, a.y, a.z);
        float x1 = gray_of(a.w, b.x, b.y);
        float x2 = gray_of(b.z, b.w, c.x);
        float x3 = gray_of(c.y, c.z, c.w);
        gr4[g] = make_float4(x0, x1, x2, x3);
        lmin = fminf(lmin, fminf(fminf(x0, x1), fminf(x2, x3)));
        lmax = fmaxf(lmax, fmaxf(fmaxf(x0, x1), fmaxf(x2, x3)));
    }
    for (int p = (ngroups << 2) + blockIdx.x * blockDim.x + t; p < npix; p += stride) {
        float gg = gray_of(in[3 * p], in[3 * p + 1], in[3 * p + 2]);
        g_gray[p] = gg;
        lmin = fminf(lmin, gg);
        lmax = fmaxf(lmax, gg);
    }

    for (int o = 16; o; o >>= 1) {
        lmin = fminf(lmin, __shfl_xor_sync(0xFFFFFFFFu, lmin, o));
        lmax = fmaxf(lmax, __shfl_xor_sync(0xFFFFFFFFu, lmax, o));
    }
    __shared__ float smin[8], smax[8];
    int wid = t >> 5, lid = t & 31;
    if (lid == 0) { smin[wid] = lmin; smax[wid] = lmax; }
    __syncthreads();
    if (t == 0) {
        float bmin = smin[0], bmax = smax[0];
        #pragma unroll
        for (int i = 1; i < (TB >> 5); i++) {
            bmin = fminf(bmin, smin[i]);
            bmax = fmaxf(bmax, smax[i]);
        }
        atomicMin(&g_min_bits, f_enc(bmin));
        atomicMax(&g_max_bits, f_enc(bmax));
    }
}

// ---------------- K2: 256-bin histogram ------------------------------------
__global__ void hist_kernel(int npix) {
    __shared__ unsigned int sh[256 * 8];
    for (int i = threadIdx.x; i < 256 * 8; i += blockDim.x) sh[i] = 0u;
    __syncthreads();

    const float vmin = f_dec(g_min_bits);
    const float vmax = f_dec(g_max_bits);
    const float scale = 256.0f / (vmax - vmin);

    unsigned int* my = sh + ((threadIdx.x >> 5) & 7) * 256;
    const int ngroups = npix >> 2;
    const int stride  = gridDim.x * blockDim.x;
    const float4* __restrict__ gr4 = (const float4*)g_gray;

    for (int g = blockIdx.x * blockDim.x + threadIdx.x; g < ngroups; g += stride) {
        float4 v = __ldcg(&gr4[g]);
        int b0 = min(255, max(0, (int)((v.x - vmin) * scale)));
        int b1 = min(255, max(0, (int)((v.y - vmin) * scale)));
        int b2 = min(255, max(0, (int)((v.z - vmin) * scale)));
        int b3 = min(255, max(0, (int)((v.w - vmin) * scale)));
        atomicAdd(&my[b0], 1u);
        atomicAdd(&my[b1], 1u);
        atomicAdd(&my[b2], 1u);
        atomicAdd(&my[b3], 1u);
    }
    for (int p = (ngroups << 2) + blockIdx.x * blockDim.x + threadIdx.x; p < npix; p += stride) {
        int b = min(255, max(0, (int)((__ldcg(&g_gray[p]) - vmin) * scale)));
        atomicAdd(&my[b], 1u);
    }
    __syncthreads();
    for (int i = threadIdx.x; i < 256; i += blockDim.x) {
        unsigned int s = 0;
        #pragma unroll
        for (int r = 0; r < 8; r++) s += sh[r * 256 + i];
        if (s) atomicAdd(&g_hist[i], s);
    }
}

// -------- K3: per-block Otsu prologue + direct binarize (2x ILP) -----------
__global__ void binarize_kernel(float* __restrict__ out, int npix) {
    __shared__ struct {
        float c[256], w1[256], s1[256], w2[256], s2[256], bv[256];
        int bi[256];
    } sh;
    __shared__ float s_thresh;
    const int t = threadIdx.x;

    // ---- Otsu prologue: every block computes threshold from g_hist ----
    {
        const float vmin = f_dec(g_min_bits);
        const float vmax = f_dec(g_max_bits);
        const float step = __fmul_rn(__fadd_rn(vmax, -vmin), 1.0f / 256.0f);

        float e0 = __fadd_rn(vmin, __fmul_rn(step, (float)t));
        float e1 = (t == 255) ? vmax : __fadd_rn(vmin, __fmul_rn(step, (float)(t + 1)));
        float ct = __fmul_rn(__fadd_rn(e0, e1), 0.5f);
        sh.c[t] = ct;

        float hv = (float)g_hist[t];
        float hc = __fmul_rn(hv, ct);
        sh.w1[t] = hv; sh.s1[t] = hc;
        sh.w2[t] = hv; sh.s2[t] = hc;
        __syncthreads();

        #pragma unroll
        for (int s = 1; s < 256; s <<= 1) {
            float aw1 = (t >= s)      ? sh.w1[t - s] : 0.0f;
            float as1 = (t >= s)      ? sh.s1[t - s] : 0.0f;
            float aw2 = (t + s < 256) ? sh.w2[t + s] : 0.0f;
            float as2 = (t + s < 256) ? sh.s2[t + s] : 0.0f;
            __syncthreads();
            sh.w1[t] = __fadd_rn(sh.w1[t], aw1);
            sh.s1[t] = __fadd_rn(sh.s1[t], as1);
            sh.w2[t] = __fadd_rn(sh.w2[t], aw2);
            sh.s2[t] = __fadd_rn(sh.s2[t], as2);
            __syncthreads();
        }

        float v = -CUDART_INF_F;
        if (t < 255) {
            float m1 = sh.s1[t] / fmaxf(sh.w1[t], 1.0f);
            float m2 = sh.s2[t + 1] / fmaxf(sh.w2[t + 1], 1.0f);
            float d = __fadd_rn(m1, -m2);
            v = __fmul_rn(__fmul_rn(sh.w1[t], sh.w2[t + 1]), __fmul_rn(d, d));
        }
        sh.bv[t] = v; sh.bi[t] = t;
        __syncthreads();
        for (int s = 128; s; s >>= 1) {
            if (t < s) {
                float ov = sh.bv[t + s]; int oi = sh.bi[t + s];
                if (ov > sh.bv[t] || (ov == sh.bv[t] && oi < sh.bi[t])) {
                    sh.bv[t] = ov; sh.bi[t] = oi;
                }
            }
            __syncthreads();
        }
        if (t == 0) s_thresh = sh.c[sh.bi[0]];
        __syncthreads();
    }

    // ---- direct streaming binarize: 2 out-float4 per iteration ----
    const float thr = s_thresh;
    const int nout4 = (npix * 3) >> 2;
    const int stride = gridDim.x * blockDim.x;
    const float* __restrict__ gray = g_gray;
    float4* __restrict__ o4 = (float4*)out;

    int f = blockIdx.x * blockDim.x + t;
    for (; f + stride < nout4; f += 2 * stride) {
        const int fA = f, fB = f + stride;
        const int eA = 4 * fA,      eB = 4 * fB;
        const int pA = eA / 3,      pB = eB / 3;
        const int rA = eA - 3 * pA, rB = eB - 3 * pB;
        float gaA = __ldg(&gray[pA]);
        float gbA = __ldg(&gray[pA + 1]);
        float gaB = __ldg(&gray[pB]);
        float gbB = __ldg(&gray[pB + 1]);
        float baA = (gaA > thr) ? 1.0f : 0.0f;
        float bbA = (gbA > thr) ? 1.0f : 0.0f;
        float baB = (gaB > thr) ? 1.0f : 0.0f;
        float bbB = (gbB > thr) ? 1.0f : 0.0f;
        float4 vA, vB;
        vA.x = baA;                    // rA+0 < 3 always
        vA.y = (rA < 2) ? baA : bbA;
        vA.z = (rA < 1) ? baA : bbA;
        vA.w = bbA;
        vB.x = baB;
        vB.y = (rB < 2) ? baB : bbB;
        vB.z = (rB < 1) ? baB : bbB;
        vB.w = bbB;
        o4[fA] = vA;
        o4[fB] = vB;
    }
    for (; f < nout4; f += stride) {
        const int e0 = 4 * f;
        const int p0 = e0 / 3;
        const int r  = e0 - 3 * p0;
        float ga = __ldg(&gray[p0]);
        float gb = __ldg(&gray[p0 + 1]);
        float ba = (ga > thr) ? 1.0f : 0.0f;
        float bb = (gb > thr) ? 1.0f : 0.0f;
        float4 v;
        v.x = ba;
        v.y = (r < 2) ? ba : bb;
        v.z = (r < 1) ? ba : bb;
        v.w = bb;
        o4[f] = v;
    }
    for (int e = (nout4 << 2) + blockIdx.x * blockDim.x + t; e < npix * 3; e += stride) {
        float g = __ldg(&gray[e / 3]);
        out[e] = (g > thr) ? 1.0f : 0.0f;
    }
}

// ---------------- launch ---------------------------------------------------
extern "C" void kernel_launch(void* const* d_in, const int* in_sizes, int n_in,
                              void* d_out, int out_size) {
    const float* in = (const float*)d_in[0];
    float* out = (float*)d_out;
    int npix = in_sizes[0] / 3;

    const int GRID = 148 * 8;

    init_kernel<<<1, 256>>>();
    gray_minmax_kernel<<<GRID, TB>>>(in, npix);
    hist_kernel<<<GRID, TB>>>(npix);
    binarize_kernel<<<GRID, TB>>>(out, npix);
}